// round 10
// baseline (speedup 1.0000x reference)
#include <cuda_runtime.h>
#include <math.h>
#include <stdint.h>

#define C_EMBED 768
#define NH 12
#define HD 64
#define BATCH 2
#define SEQ 4096
#define MROWS (BATCH*SEQ)        // 8192
#define C3 (3*C_EMBED)           // 2304

// Scratch (no allocations allowed) — tf32 bit buffers
__device__ __align__(16) uint32_t g_qkv[(size_t)MROWS * C3];          // 75.5 MB
__device__ __align__(16) uint32_t g_att[(size_t)MROWS * C_EMBED];     // 25 MB
__device__ __align__(16) uint32_t g_xt[(size_t)MROWS * C_EMBED];      // 25 MB
__device__ __align__(16) uint32_t g_wqkvt[(size_t)C_EMBED * C3];      // 7 MB
__device__ __align__(16) uint32_t g_wprojt[(size_t)C_EMBED * C_EMBED];// 2.4 MB

// ---------------------------------------------------------------------------
// helpers
// ---------------------------------------------------------------------------
__device__ __forceinline__ uint32_t f2tf32(float v) {
    uint32_t t;
    asm("cvt.rna.tf32.f32 %0, %1;" : "=r"(t) : "f"(v));
    return t;
}

__device__ __forceinline__ void mma16n8k8(float* d, const uint32_t* a, const uint32_t* b) {
    asm volatile(
        "mma.sync.aligned.m16n8k8.row.col.f32.tf32.tf32.f32 "
        "{%0,%1,%2,%3}, {%4,%5,%6,%7}, {%8,%9}, {%0,%1,%2,%3};"
        : "+f"(d[0]), "+f"(d[1]), "+f"(d[2]), "+f"(d[3])
        : "r"(a[0]), "r"(a[1]), "r"(a[2]), "r"(a[3]), "r"(b[0]), "r"(b[1]));
}

// one instruction -> 4 fragment registers (8x4 tf32 blocks)
__device__ __forceinline__ void ldmx4(uint32_t* r, uint32_t a) {
    asm volatile("ldmatrix.sync.aligned.m8n8.x4.shared.b16 {%0,%1,%2,%3}, [%4];"
                 : "=r"(r[0]), "=r"(r[1]), "=r"(r[2]), "=r"(r[3]) : "r"(a));
}

__device__ __forceinline__ uint32_t smem_u32(const void* p) {
    uint32_t a;
    asm("{ .reg .u64 t; cvta.to.shared.u64 t, %1; cvt.u32.u64 %0, t; }"
        : "=r"(a) : "l"(p));
    return a;
}

__device__ __forceinline__ void cp_async16(uint32_t saddr, const void* gptr) {
    asm volatile("cp.async.ca.shared.global [%0], [%1], 16;"
                 :: "r"(saddr), "l"(gptr));
}
__device__ __forceinline__ void cp_commit() {
    asm volatile("cp.async.commit_group;" ::: "memory");
}
__device__ __forceinline__ void cp_wait1() {
    asm volatile("cp.async.wait_group 1;" ::: "memory");
}
__device__ __forceinline__ void cp_wait0() {
    asm volatile("cp.async.wait_group 0;" ::: "memory");
}

// ---------------------------------------------------------------------------
// elementwise fp32 -> tf32-bits pre-pass
// ---------------------------------------------------------------------------
__global__ void __launch_bounds__(256) cvt_tf32_kernel(
    const float4* __restrict__ in, uint4* __restrict__ out, int n4)
{
    int i = blockIdx.x * blockDim.x + threadIdx.x;
    if (i < n4) {
        float4 v = in[i];
        uint4 t;
        t.x = f2tf32(v.x); t.y = f2tf32(v.y);
        t.z = f2tf32(v.z); t.w = f2tf32(v.w);
        out[i] = t;
    }
}

// ===========================================================================
// tf32-bit mma GEMM, 2-stage cp.async (verified R7/R9 structure) + A via
// ldmatrix. C = A@B + bias. MODE 0: fp32 out. MODE 1: tf32-bit out, Q-scaled.
// ===========================================================================
#define G_AW 36
#define G_BW 136
#define G_ABUF (128 * G_AW)
#define G_BBUF (32 * G_BW)
#define G_BOFF (2 * G_ABUF)
#define GEMM_SMEM_BYTES ((2 * G_ABUF + 2 * G_BBUF) * 4)   // 71680

template<int MODE>
__global__ void __launch_bounds__(256, 2) gemm_tf32_kernel(
    const uint32_t* __restrict__ A, const uint32_t* __restrict__ Bm,
    const float* __restrict__ bias, float* __restrict__ Cm,
    int M, int N, int K)
{
    extern __shared__ uint32_t gsm[];
    const uint32_t sb = smem_u32(gsm);

    const int tid = threadIdx.x;
    const int w   = tid >> 5;
    const int L   = tid & 31;
    const int gid = L >> 2;
    const int tig = L & 3;
    const int row0 = blockIdx.y * 128;
    const int col0 = blockIdx.x * 128;
    const int m0w = (w & 1) * 64;
    const int n0w = (w >> 1) * 32;
    const int nk = K >> 5;

    // ldmatrix lane mapping for A fragments:
    // mat0 rows+0 k+0 | mat1 rows+8 k+0 | mat2 rows+0 k+4 | mat3 rows+8 k+4
    const int am = L >> 3;
    const int arow_off = ((am & 1) << 3) + (L & 7);
    const int acol_off = (am >> 1) << 2;

    float acc[4][4][4];
#pragma unroll
    for (int mt = 0; mt < 4; mt++)
#pragma unroll
        for (int nt = 0; nt < 4; nt++)
#pragma unroll
            for (int e = 0; e < 4; e++) acc[mt][nt][e] = 0.f;

    auto issue = [&](int t, int bf) {
        const int kb = t * 32;
#pragma unroll
        for (int u = 0; u < 4; u++) {
            int fid = u * 256 + tid;
            int r   = fid >> 3;
            int c4  = fid & 7;
            cp_async16(sb + (uint32_t)((bf * G_ABUF + r * G_AW + c4 * 4) * 4),
                       &A[(size_t)(row0 + r) * K + kb + c4 * 4]);
        }
#pragma unroll
        for (int u = 0; u < 4; u++) {
            int fid = u * 256 + tid;
            int k   = fid >> 5;
            int n4  = fid & 31;
            cp_async16(sb + (uint32_t)((G_BOFF + bf * G_BBUF + k * G_BW + n4 * 4) * 4),
                       &Bm[(size_t)(kb + k) * N + col0 + n4 * 4]);
        }
    };

    issue(0, 0);
    cp_commit();

    for (int t = 0; t < nk; t++) {
        const int bf = t & 1;
        if (t + 1 < nk) { issue(t + 1, bf ^ 1); cp_commit(); cp_wait1(); }
        else            { cp_wait0(); }
        __syncthreads();

        const uint32_t sbA = sb + (uint32_t)(bf * G_ABUF * 4);
        const uint32_t* Bf = gsm + G_BOFF + bf * G_BBUF;

#pragma unroll
        for (int ks = 0; ks < 4; ks++) {
            const int k0 = ks * 8;
            uint32_t af[4][4];
#pragma unroll
            for (int mt = 0; mt < 4; mt++) {
                ldmx4(af[mt], sbA + (uint32_t)(((m0w + mt * 16 + arow_off) * G_AW
                                                + k0 + acol_off) * 4));
            }
            uint32_t bfr[4][2];
#pragma unroll
            for (int nt = 0; nt < 4; nt++) {
                const int n = n0w + nt * 8 + gid;
                bfr[nt][0] = Bf[(k0 + tig) * G_BW + n];
                bfr[nt][1] = Bf[(k0 + tig + 4) * G_BW + n];
            }
#pragma unroll
            for (int mt = 0; mt < 4; mt++)
#pragma unroll
                for (int nt = 0; nt < 4; nt++)
                    mma16n8k8(acc[mt][nt], af[mt], bfr[nt]);
        }
        __syncthreads();
    }

    // epilogue
#pragma unroll
    for (int mt = 0; mt < 4; mt++) {
        const int r = row0 + m0w + mt * 16 + gid;
#pragma unroll
        for (int nt = 0; nt < 4; nt++) {
            const int c = col0 + n0w + nt * 8 + 2 * tig;
            const float b0 = bias[c], b1 = bias[c + 1];
            if (MODE == 0) {
                float2 v0 = make_float2(acc[mt][nt][0] + b0, acc[mt][nt][1] + b1);
                *(float2*)&Cm[(size_t)r * N + c] = v0;
                float2 v1 = make_float2(acc[mt][nt][2] + b0, acc[mt][nt][3] + b1);
                *(float2*)&Cm[(size_t)(r + 8) * N + c] = v1;
            } else {
                const float sc = (c < C_EMBED) ? 0.125f : 1.0f;   // Q-scale fold
                uint32_t* Co = (uint32_t*)Cm;
                uint2 v0, v1;
                v0.x = f2tf32((acc[mt][nt][0] + b0) * sc);
                v0.y = f2tf32((acc[mt][nt][1] + b1) * sc);
                v1.x = f2tf32((acc[mt][nt][2] + b0) * sc);
                v1.y = f2tf32((acc[mt][nt][3] + b1) * sc);
                *(uint2*)&Co[(size_t)r * N + c] = v0;
                *(uint2*)&Co[(size_t)(r + 8) * N + c] = v1;
            }
        }
    }
}

// ===========================================================================
// tf32-bit mma flash attention (causal), 128-row Q tiles, cp.async K/V,
// single barrier per key tile, largest-qt-first, K/P via ldmatrix.
// NEW: __launch_bounds__(256, 2) -> regs capped at 128 so 2 CTAs co-reside
// per SM (2 x 104 KB smem, full RF). Softmax of one CTA overlaps mma of the
// other.
// ===========================================================================
#define A_KW 68
#define A_VW 72
#define A_KBUF (64 * A_KW)
#define A_VBUF (64 * A_VW)
#define A_VOFF (2 * A_KBUF)
#define A_POFF (A_VOFF + 2 * A_VBUF)
#define ATTN_SMEM_BYTES ((A_POFF + 128 * 68) * 4)   // 106496

__global__ void __launch_bounds__(256, 2) attn_tc_kernel(
    const uint32_t* __restrict__ qkv, uint32_t* __restrict__ attout)
{
    extern __shared__ uint32_t asm_[];
    const uint32_t sb = smem_u32(asm_);
    uint32_t* Ps = asm_ + A_POFF;
    const uint32_t sbP = sb + (uint32_t)(A_POFF * 4);

    const int qt  = (int)gridDim.x - 1 - (int)blockIdx.x;   // largest-first
    const int h   = blockIdx.y;
    const int b   = blockIdx.z;
    const int tid = threadIdx.x;
    const int w   = tid >> 5;
    const int L   = tid & 31;
    const int gid = L >> 2;
    const int tig = L & 3;
    const int wrow = w * 16;

    // ldmatrix lane maps
    // K: mat0 rows+0 k+0 | mat1 rows+0 k+4 | mat2 rows+8 k+0 | mat3 rows+8 k+4
    const int km = L >> 3;
    const int krow_off = ((km >> 1) << 3) + (L & 7);
    const int kcol_off = (km & 1) << 2;
    // P: mat0 rows+0 k+0 | mat1 rows+8 k+0 | mat2 rows+0 k+4 | mat3 rows+8 k+4
    const int pm = L >> 3;
    const int prow_off = ((pm & 1) << 3) + (L & 7);
    const int pcol_off = (pm >> 1) << 2;

    const uint32_t* qbase = qkv + (size_t)b * SEQ * C3 + h * HD;
    const uint32_t* kbase = qbase + C_EMBED;
    const uint32_t* vbase = qbase + 2 * C_EMBED;

    // ---- Q fragments: ready tf32 bits straight from gmem ----
    uint32_t qf[8][4];
    {
        const uint32_t* qr0 = qbase + (size_t)(qt * 128 + wrow + gid) * C3;
        const uint32_t* qr1 = qr0 + 8 * C3;
#pragma unroll
        for (int ks = 0; ks < 8; ks++) {
            const int c = 8 * ks + tig;
            qf[ks][0] = qr0[c];
            qf[ks][1] = qr1[c];
            qf[ks][2] = qr0[c + 4];
            qf[ks][3] = qr1[c + 4];
        }
    }

    float o[8][4];
#pragma unroll
    for (int nt = 0; nt < 8; nt++)
#pragma unroll
        for (int e = 0; e < 4; e++) o[nt][e] = 0.f;
    float m0 = -1e30f, m1 = -1e30f, l0 = 0.f, l1 = 0.f;

    const int rmax_w = qt * 128 + wrow + 15;
    const int ntiles = 2 * qt + 2;

    auto issue = [&](int j, int bf) {
#pragma unroll
        for (int u = 0; u < 4; u++) {
            int fid = u * 256 + tid;
            int r   = fid >> 4;
            int c4  = fid & 15;
            const size_t grow = (size_t)(j * 64 + r) * C3 + c4 * 4;
            cp_async16(sb + (uint32_t)((bf * A_KBUF + r * A_KW + c4 * 4) * 4),
                       kbase + grow);
            cp_async16(sb + (uint32_t)((A_VOFF + bf * A_VBUF + r * A_VW + c4 * 4) * 4),
                       vbase + grow);
        }
    };

    issue(0, 0);
    cp_commit();

    for (int j0 = 0; j0 < ntiles; j0++) {
        cp_wait0();
        __syncthreads();
        if (j0 + 1 < ntiles) { issue(j0 + 1, (j0 + 1) & 1); cp_commit(); }

        if (j0 * 64 <= rmax_w) {
            const int bf = j0 & 1;
            const uint32_t sbK = sb + (uint32_t)(bf * A_KBUF * 4);
            const uint32_t* Vf = asm_ + A_VOFF + bf * A_VBUF;

            // ---- S = Q K^T (K fragments via ldmatrix.x4) ----
            float s[8][4];
#pragma unroll
            for (int nt = 0; nt < 8; nt++)
#pragma unroll
                for (int e = 0; e < 4; e++) s[nt][e] = 0.f;

#pragma unroll
            for (int ks = 0; ks < 8; ks++) {
#pragma unroll
                for (int ntp = 0; ntp < 4; ntp++) {
                    uint32_t kb4[4];
                    ldmx4(kb4, sbK + (uint32_t)(((ntp * 16 + krow_off) * A_KW
                                                 + 8 * ks + kcol_off) * 4));
                    mma16n8k8(s[2 * ntp],     qf[ks], kb4);
                    mma16n8k8(s[2 * ntp + 1], qf[ks], kb4 + 2);
                }
            }

            // ---- causal mask ----
            const int qr0 = qt * 128 + wrow + gid;
            if (j0 * 64 + 63 > qt * 128 + wrow) {
#pragma unroll
                for (int nt = 0; nt < 8; nt++) {
                    const int c0g = j0 * 64 + nt * 8 + 2 * tig;
                    if (c0g     > qr0)     s[nt][0] = -1e30f;
                    if (c0g + 1 > qr0)     s[nt][1] = -1e30f;
                    if (c0g     > qr0 + 8) s[nt][2] = -1e30f;
                    if (c0g + 1 > qr0 + 8) s[nt][3] = -1e30f;
                }
            }

            // ---- online softmax ----
            float mloc0 = -1e30f, mloc1 = -1e30f;
#pragma unroll
            for (int nt = 0; nt < 8; nt++) {
                mloc0 = fmaxf(mloc0, fmaxf(s[nt][0], s[nt][1]));
                mloc1 = fmaxf(mloc1, fmaxf(s[nt][2], s[nt][3]));
            }
            mloc0 = fmaxf(mloc0, __shfl_xor_sync(0xffffffffu, mloc0, 1));
            mloc0 = fmaxf(mloc0, __shfl_xor_sync(0xffffffffu, mloc0, 2));
            mloc1 = fmaxf(mloc1, __shfl_xor_sync(0xffffffffu, mloc1, 1));
            mloc1 = fmaxf(mloc1, __shfl_xor_sync(0xffffffffu, mloc1, 2));

            const float mn0 = fmaxf(m0, mloc0);
            const float mn1 = fmaxf(m1, mloc1);
            const float cr0 = __expf(m0 - mn0);
            const float cr1 = __expf(m1 - mn1);

            float rs0 = 0.f, rs1 = 0.f;
#pragma unroll
            for (int nt = 0; nt < 8; nt++) {
                s[nt][0] = __expf(s[nt][0] - mn0);
                s[nt][1] = __expf(s[nt][1] - mn0);
                s[nt][2] = __expf(s[nt][2] - mn1);
                s[nt][3] = __expf(s[nt][3] - mn1);
                rs0 += s[nt][0] + s[nt][1];
                rs1 += s[nt][2] + s[nt][3];
            }
            rs0 += __shfl_xor_sync(0xffffffffu, rs0, 1);
            rs0 += __shfl_xor_sync(0xffffffffu, rs0, 2);
            rs1 += __shfl_xor_sync(0xffffffffu, rs1, 1);
            rs1 += __shfl_xor_sync(0xffffffffu, rs1, 2);

            l0 = l0 * cr0 + rs0;
            l1 = l1 * cr1 + rs1;
            m0 = mn0;
            m1 = mn1;
#pragma unroll
            for (int nt = 0; nt < 8; nt++) {
                o[nt][0] *= cr0; o[nt][1] *= cr0;
                o[nt][2] *= cr1; o[nt][3] *= cr1;
            }

            // ---- stage P (warp-private rows) ----
#pragma unroll
            for (int nt = 0; nt < 8; nt++) {
                const int pb = (wrow + gid) * 68 + nt * 8 + 2 * tig;
                Ps[pb]              = f2tf32(s[nt][0]);
                Ps[pb + 1]          = f2tf32(s[nt][1]);
                Ps[pb + 8 * 68]     = f2tf32(s[nt][2]);
                Ps[pb + 8 * 68 + 1] = f2tf32(s[nt][3]);
            }
            __syncwarp();

            // ---- O += P V (P fragments via ldmatrix.x4) ----
#pragma unroll
            for (int ks = 0; ks < 8; ks++) {
                uint32_t pa[4];
                ldmx4(pa, sbP + (uint32_t)(((wrow + prow_off) * 68
                                            + 8 * ks + pcol_off) * 4));
#pragma unroll
                for (int nt = 0; nt < 8; nt++) {
                    uint32_t vb[2];
                    const int rv = (8 * ks + tig) * A_VW + nt * 8 + gid;
                    vb[0] = Vf[rv];
                    vb[1] = Vf[rv + 4 * A_VW];
                    mma16n8k8(o[nt], pa, vb);
                }
            }
            __syncwarp();
        }
    }

    // ---- normalize + write tf32 bits ----
    const float inv0 = 1.f / l0;
    const float inv1 = 1.f / l1;
    const int t0 = qt * 128 + wrow + gid;
#pragma unroll
    for (int nt = 0; nt < 8; nt++) {
        const int d = h * HD + nt * 8 + 2 * tig;
        uint2 v0, v1;
        v0.x = f2tf32(o[nt][0] * inv0);
        v0.y = f2tf32(o[nt][1] * inv0);
        v1.x = f2tf32(o[nt][2] * inv1);
        v1.y = f2tf32(o[nt][3] * inv1);
        *(uint2*)&attout[(size_t)(b * SEQ + t0) * C_EMBED + d] = v0;
        *(uint2*)&attout[(size_t)(b * SEQ + t0 + 8) * C_EMBED + d] = v1;
    }
}

// ---------------------------------------------------------------------------
extern "C" void kernel_launch(void* const* d_in, const int* in_sizes, int n_in,
                              void* d_out, int out_size)
{
    const float* x     = (const float*)d_in[0];
    const float* Wqkv  = (const float*)d_in[1];
    const float* bqkv  = (const float*)d_in[2];
    const float* Wproj = (const float*)d_in[3];
    const float* bproj = (const float*)d_in[4];
    float* out = (float*)d_out;

    uint32_t *qkv, *att, *xt, *wqkvt, *wprojt;
    cudaGetSymbolAddress((void**)&qkv, g_qkv);
    cudaGetSymbolAddress((void**)&att, g_att);
    cudaGetSymbolAddress((void**)&xt, g_xt);
    cudaGetSymbolAddress((void**)&wqkvt, g_wqkvt);
    cudaGetSymbolAddress((void**)&wprojt, g_wprojt);

    cudaFuncSetAttribute(gemm_tf32_kernel<0>, cudaFuncAttributeMaxDynamicSharedMemorySize,
                         GEMM_SMEM_BYTES);
    cudaFuncSetAttribute(gemm_tf32_kernel<1>, cudaFuncAttributeMaxDynamicSharedMemorySize,
                         GEMM_SMEM_BYTES);
    cudaFuncSetAttribute(attn_tc_kernel, cudaFuncAttributeMaxDynamicSharedMemorySize,
                         ATTN_SMEM_BYTES);

    // 0) pre-round inputs/weights to tf32 bits
    {
        int n4x = (MROWS * C_EMBED) / 4;
        cvt_tf32_kernel<<<(n4x + 255) / 256, 256>>>((const float4*)x, (uint4*)xt, n4x);
        int n4w = (C_EMBED * C3) / 4;
        cvt_tf32_kernel<<<(n4w + 255) / 256, 256>>>((const float4*)Wqkv, (uint4*)wqkvt, n4w);
        int n4p = (C_EMBED * C_EMBED) / 4;
        cvt_tf32_kernel<<<(n4p + 255) / 256, 256>>>((const float4*)Wproj, (uint4*)wprojt, n4p);
    }

    // 1) QKV projection -> tf32 bits, Q-scale folded
    dim3 g1(C3 / 128, MROWS / 128);
    gemm_tf32_kernel<1><<<g1, 256, GEMM_SMEM_BYTES>>>(xt, wqkvt, bqkv, (float*)qkv,
                                                      MROWS, C3, C_EMBED);

    // 2) Causal flash attention -> tf32 bits
    dim3 g2(SEQ / 128, NH, BATCH);
    attn_tc_kernel<<<g2, 256, ATTN_SMEM_BYTES>>>(qkv, att);

    // 3) Output projection -> fp32
    dim3 g3(C_EMBED / 128, MROWS / 128);
    gemm_tf32_kernel<0><<<g3, 256, GEMM_SMEM_BYTES>>>(att, wprojt, bproj, out,
                                                      MROWS, C_EMBED, C_EMBED);
}